// round 3
// baseline (speedup 1.0000x reference)
#include <cuda_runtime.h>
#include <cstdint>

// TransD scoring kernel, round 3: cp.async (LDGSTS) gathers.
// out[b] = rp * (dot(hp,h) - dot(tp,t)) + (h - t) + r
// ENT_DIM = REL_DIM = 128, BATCH = 16384.
//
// Warp handles 2 batch elems. The 8 entity rows (h,t,hp,tp x2) are fetched
// with cp.async.cg 16B-per-lane into a per-warp smem slab: no registers held
// per outstanding byte -> high occupancy AND deep MLP simultaneously.

#define BATCH 16384
#define WARPS_PER_BLOCK 8
#define ELEMS_PER_WARP 2
#define ROWS_PER_WARP 8           // 4 rows per elem
#define ROW_BYTES 512

__device__ __forceinline__ float warp_sum(float v) {
    v += __shfl_xor_sync(0xFFFFFFFFu, v, 16);
    v += __shfl_xor_sync(0xFFFFFFFFu, v, 8);
    v += __shfl_xor_sync(0xFFFFFFFFu, v, 4);
    v += __shfl_xor_sync(0xFFFFFFFFu, v, 2);
    v += __shfl_xor_sync(0xFFFFFFFFu, v, 1);
    return v;
}

__device__ __forceinline__ void cp_async16(uint32_t smem_addr, const void* gptr) {
    asm volatile("cp.async.cg.shared.global [%0], [%1], 16;\n"
                 :: "r"(smem_addr), "l"(gptr));
}

__global__ __launch_bounds__(256)
void transd_kernel(const int* __restrict__ head,
                   const int* __restrict__ relation,
                   const int* __restrict__ tail,
                   const float* __restrict__ ent_emb,
                   const float* __restrict__ ent_map_emb,
                   const float4* __restrict__ rel_emb,
                   const float4* __restrict__ rel_map_emb,
                   float4* __restrict__ out)
{
    // Per-warp slab: 8 rows x 512B = 4KB. Block: 8 warps -> 32KB.
    __shared__ float4 buf[WARPS_PER_BLOCK][ROWS_PER_WARP][32];

    const int wid  = threadIdx.x >> 5;
    const int lane = threadIdx.x & 31;
    const int warp_global = blockIdx.x * WARPS_PER_BLOCK + wid;

    const int b0 = warp_global * ELEMS_PER_WARP;
    const int b1 = b0 + 1;

    const int h0 = head[b0], h1 = head[b1];
    const int t0 = tail[b0], t1 = tail[b1];
    const int r0 = relation[b0], r1 = relation[b1];

    // Shared-memory destination addresses for this lane.
    uint32_t s_base;
    {
        const float4* p = &buf[wid][0][lane];
        asm("{ .reg .u64 t; cvta.to.shared.u64 t, %1; cvt.u32.u64 %0, t; }"
            : "=r"(s_base) : "l"(p));
    }

    // Global row base pointers (row = idx * 512 bytes), this lane's 16B chunk.
    const char* e  = (const char*)ent_emb;
    const char* em = (const char*)ent_map_emb;
    const int lb = lane * 16;

    // Issue 8 independent 16B cp.async per lane = 8 x 512B rows per warp.
    cp_async16(s_base + 0 * ROW_BYTES, e  + (long)h0 * ROW_BYTES + lb);
    cp_async16(s_base + 1 * ROW_BYTES, e  + (long)t0 * ROW_BYTES + lb);
    cp_async16(s_base + 2 * ROW_BYTES, em + (long)h0 * ROW_BYTES + lb);
    cp_async16(s_base + 3 * ROW_BYTES, em + (long)t0 * ROW_BYTES + lb);
    cp_async16(s_base + 4 * ROW_BYTES, e  + (long)h1 * ROW_BYTES + lb);
    cp_async16(s_base + 5 * ROW_BYTES, e  + (long)t1 * ROW_BYTES + lb);
    cp_async16(s_base + 6 * ROW_BYTES, em + (long)h1 * ROW_BYTES + lb);
    cp_async16(s_base + 7 * ROW_BYTES, em + (long)t1 * ROW_BYTES + lb);
    asm volatile("cp.async.commit_group;\n" ::: "memory");

    // Overlap: relation rows (L2-resident) via normal loads while gathers fly.
    const long ro0 = (long)r0 * 32 + lane;
    const long ro1 = (long)r1 * 32 + lane;
    const float4 vr0  = __ldg(&rel_emb[ro0]);
    const float4 vr1  = __ldg(&rel_emb[ro1]);
    const float4 vrp0 = __ldg(&rel_map_emb[ro0]);
    const float4 vrp1 = __ldg(&rel_map_emb[ro1]);

    asm volatile("cp.async.wait_group 0;\n" ::: "memory");
    __syncwarp();

    // Compute elem 0.
    const float4 vh0  = buf[wid][0][lane];
    const float4 vt0  = buf[wid][1][lane];
    const float4 vhp0 = buf[wid][2][lane];
    const float4 vtp0 = buf[wid][3][lane];
    const float4 vh1  = buf[wid][4][lane];
    const float4 vt1  = buf[wid][5][lane];
    const float4 vhp1 = buf[wid][6][lane];
    const float4 vtp1 = buf[wid][7][lane];

    float dh0 = vh0.x * vhp0.x + vh0.y * vhp0.y + vh0.z * vhp0.z + vh0.w * vhp0.w;
    float dt0 = vt0.x * vtp0.x + vt0.y * vtp0.y + vt0.z * vtp0.z + vt0.w * vtp0.w;
    float dh1 = vh1.x * vhp1.x + vh1.y * vhp1.y + vh1.z * vhp1.z + vh1.w * vhp1.w;
    float dt1 = vt1.x * vtp1.x + vt1.y * vtp1.y + vt1.z * vtp1.z + vt1.w * vtp1.w;

    const float d0 = warp_sum(dh0 - dt0);
    const float d1 = warp_sum(dh1 - dt1);

    float4 o0, o1;
    o0.x = fmaf(vrp0.x, d0, vh0.x - vt0.x + vr0.x);
    o0.y = fmaf(vrp0.y, d0, vh0.y - vt0.y + vr0.y);
    o0.z = fmaf(vrp0.z, d0, vh0.z - vt0.z + vr0.z);
    o0.w = fmaf(vrp0.w, d0, vh0.w - vt0.w + vr0.w);
    o1.x = fmaf(vrp1.x, d1, vh1.x - vt1.x + vr1.x);
    o1.y = fmaf(vrp1.y, d1, vh1.y - vt1.y + vr1.y);
    o1.z = fmaf(vrp1.z, d1, vh1.z - vt1.z + vr1.z);
    o1.w = fmaf(vrp1.w, d1, vh1.w - vt1.w + vr1.w);

    out[(long)b0 * 32 + lane] = o0;
    out[(long)b1 * 32 + lane] = o1;
}

extern "C" void kernel_launch(void* const* d_in, const int* in_sizes, int n_in,
                              void* d_out, int out_size)
{
    const int*    head    = (const int*)d_in[0];
    const int*    rel     = (const int*)d_in[1];
    const int*    tail    = (const int*)d_in[2];
    const float*  ent     = (const float*)d_in[3];
    const float*  ent_map = (const float*)d_in[4];
    const float4* rel_emb = (const float4*)d_in[5];
    const float4* rel_map = (const float4*)d_in[6];
    float4*       out     = (float4*)d_out;

    const int threads = 256;  // 8 warps x 2 elems = 16 elems/block
    const int blocks  = BATCH / (WARPS_PER_BLOCK * ELEMS_PER_WARP);  // 1024
    transd_kernel<<<blocks, threads>>>(head, rel, tail, ent, ent_map,
                                       rel_emb, rel_map, out);
}

// round 4
// speedup vs baseline: 1.2648x; 1.2648x over previous
#include <cuda_runtime.h>
#include <cstdint>

// TransD scoring kernel, round 4: TMA bulk-copy gathers.
// out[b] = rp * (dot(hp,h) - dot(tp,t)) + (h - t) + r
// ENT_DIM = REL_DIM = 128, BATCH = 16384.
//
// Entity row gathers issued as cp.async.bulk (512B each) by one elected lane
// per warp, completing on a per-warp smem mbarrier. This bypasses the SM's
// LDG/L1 fill-queue (the suspected ~45-line/SM concurrency cap seen in R1-R3)
// and uses the TMA/bulk engine's own queues into L2.

#define BATCH 16384
#define WARPS_PER_BLOCK 8
#define ELEMS_PER_WARP 2
#define ROWS_PER_WARP 8
#define ROW_BYTES 512

__device__ __forceinline__ float warp_sum(float v) {
    v += __shfl_xor_sync(0xFFFFFFFFu, v, 16);
    v += __shfl_xor_sync(0xFFFFFFFFu, v, 8);
    v += __shfl_xor_sync(0xFFFFFFFFu, v, 4);
    v += __shfl_xor_sync(0xFFFFFFFFu, v, 2);
    v += __shfl_xor_sync(0xFFFFFFFFu, v, 1);
    return v;
}

__device__ __forceinline__ uint32_t smem_u32(const void* p) {
    uint32_t a;
    asm("{ .reg .u64 t; cvta.to.shared.u64 t, %1; cvt.u32.u64 %0, t; }"
        : "=r"(a) : "l"(p));
    return a;
}

__device__ __forceinline__ void bulk_ld(uint32_t s_dst, const void* g_src,
                                        uint32_t bytes, uint32_t mbar) {
    asm volatile(
        "cp.async.bulk.shared::cta.global.mbarrier::complete_tx::bytes "
        "[%0], [%1], %2, [%3];\n"
        :: "r"(s_dst), "l"(g_src), "r"(bytes), "r"(mbar) : "memory");
}

__device__ __forceinline__ void mbar_init(uint32_t mbar, uint32_t count) {
    asm volatile("mbarrier.init.shared.b64 [%0], %1;\n" :: "r"(mbar), "r"(count) : "memory");
}

__device__ __forceinline__ void mbar_expect_tx(uint32_t mbar, uint32_t bytes) {
    asm volatile("mbarrier.arrive.expect_tx.shared.b64 _, [%0], %1;\n"
                 :: "r"(mbar), "r"(bytes) : "memory");
}

__device__ __forceinline__ void mbar_wait(uint32_t mbar, uint32_t parity) {
    uint32_t done;
    asm volatile(
        "{\n\t"
        ".reg .pred p;\n\t"
        "mbarrier.try_wait.parity.acquire.cta.shared::cta.b64 p, [%1], %2;\n\t"
        "selp.b32 %0, 1, 0, p;\n\t"
        "}"
        : "=r"(done) : "r"(mbar), "r"(parity) : "memory");
    if (!done) {
        asm volatile(
            "{\n\t"
            ".reg .pred P1;\n\t"
            "WAIT_LOOP_%=:\n\t"
            "mbarrier.try_wait.parity.acquire.cta.shared::cta.b64 P1, [%0], %1, 0x989680;\n\t"
            "@P1 bra.uni WAIT_DONE_%=;\n\t"
            "bra.uni WAIT_LOOP_%=;\n\t"
            "WAIT_DONE_%=:\n\t"
            "}"
            :: "r"(mbar), "r"(parity) : "memory");
    }
}

__global__ __launch_bounds__(256)
void transd_kernel(const int* __restrict__ head,
                   const int* __restrict__ relation,
                   const int* __restrict__ tail,
                   const char* __restrict__ ent_emb,
                   const char* __restrict__ ent_map_emb,
                   const float4* __restrict__ rel_emb,
                   const float4* __restrict__ rel_map_emb,
                   float4* __restrict__ out)
{
    __shared__ __align__(128) float4 buf[WARPS_PER_BLOCK][ROWS_PER_WARP][32];
    __shared__ __align__(8) unsigned long long mbar_store[WARPS_PER_BLOCK];

    const int wid  = threadIdx.x >> 5;
    const int lane = threadIdx.x & 31;
    const int warp_global = blockIdx.x * WARPS_PER_BLOCK + wid;

    const int b0 = warp_global * ELEMS_PER_WARP;
    const int b1 = b0 + 1;

    const int h0 = head[b0], h1 = head[b1];
    const int t0 = tail[b0], t1 = tail[b1];
    const int r0 = relation[b0], r1 = relation[b1];

    const uint32_t mbar = smem_u32(&mbar_store[wid]);
    const uint32_t s_row0 = smem_u32(&buf[wid][0][0]);

    if (lane == 0) {
        mbar_init(mbar, 1);
        // init is a shared-mem store by this thread; bulk ops below are issued
        // by the same thread, ordering via fence.proxy.async.
        asm volatile("fence.proxy.async.shared::cta;\n" ::: "memory");
        mbar_expect_tx(mbar, ROWS_PER_WARP * ROW_BYTES);
        bulk_ld(s_row0 + 0 * ROW_BYTES, ent_emb     + (long)h0 * ROW_BYTES, ROW_BYTES, mbar);
        bulk_ld(s_row0 + 1 * ROW_BYTES, ent_emb     + (long)t0 * ROW_BYTES, ROW_BYTES, mbar);
        bulk_ld(s_row0 + 2 * ROW_BYTES, ent_map_emb + (long)h0 * ROW_BYTES, ROW_BYTES, mbar);
        bulk_ld(s_row0 + 3 * ROW_BYTES, ent_map_emb + (long)t0 * ROW_BYTES, ROW_BYTES, mbar);
        bulk_ld(s_row0 + 4 * ROW_BYTES, ent_emb     + (long)h1 * ROW_BYTES, ROW_BYTES, mbar);
        bulk_ld(s_row0 + 5 * ROW_BYTES, ent_emb     + (long)t1 * ROW_BYTES, ROW_BYTES, mbar);
        bulk_ld(s_row0 + 6 * ROW_BYTES, ent_map_emb + (long)h1 * ROW_BYTES, ROW_BYTES, mbar);
        bulk_ld(s_row0 + 7 * ROW_BYTES, ent_map_emb + (long)t1 * ROW_BYTES, ROW_BYTES, mbar);
    }

    // Overlap: relation rows (L2-resident) while bulk gathers are in flight.
    const long ro0 = (long)r0 * 32 + lane;
    const long ro1 = (long)r1 * 32 + lane;
    const float4 vr0  = __ldg(&rel_emb[ro0]);
    const float4 vr1  = __ldg(&rel_emb[ro1]);
    const float4 vrp0 = __ldg(&rel_map_emb[ro0]);
    const float4 vrp1 = __ldg(&rel_map_emb[ro1]);

    __syncwarp();
    mbar_wait(mbar, 0);

    const float4 vh0  = buf[wid][0][lane];
    const float4 vt0  = buf[wid][1][lane];
    const float4 vhp0 = buf[wid][2][lane];
    const float4 vtp0 = buf[wid][3][lane];
    const float4 vh1  = buf[wid][4][lane];
    const float4 vt1  = buf[wid][5][lane];
    const float4 vhp1 = buf[wid][6][lane];
    const float4 vtp1 = buf[wid][7][lane];

    float dh0 = vh0.x * vhp0.x + vh0.y * vhp0.y + vh0.z * vhp0.z + vh0.w * vhp0.w;
    float dt0 = vt0.x * vtp0.x + vt0.y * vtp0.y + vt0.z * vtp0.z + vt0.w * vtp0.w;
    float dh1 = vh1.x * vhp1.x + vh1.y * vhp1.y + vh1.z * vhp1.z + vh1.w * vhp1.w;
    float dt1 = vt1.x * vtp1.x + vt1.y * vtp1.y + vt1.z * vtp1.z + vt1.w * vtp1.w;

    const float d0 = warp_sum(dh0 - dt0);
    const float d1 = warp_sum(dh1 - dt1);

    float4 o0, o1;
    o0.x = fmaf(vrp0.x, d0, vh0.x - vt0.x + vr0.x);
    o0.y = fmaf(vrp0.y, d0, vh0.y - vt0.y + vr0.y);
    o0.z = fmaf(vrp0.z, d0, vh0.z - vt0.z + vr0.z);
    o0.w = fmaf(vrp0.w, d0, vh0.w - vt0.w + vr0.w);
    o1.x = fmaf(vrp1.x, d1, vh1.x - vt1.x + vr1.x);
    o1.y = fmaf(vrp1.y, d1, vh1.y - vt1.y + vr1.y);
    o1.z = fmaf(vrp1.z, d1, vh1.z - vt1.z + vr1.z);
    o1.w = fmaf(vrp1.w, d1, vh1.w - vt1.w + vr1.w);

    out[(long)b0 * 32 + lane] = o0;
    out[(long)b1 * 32 + lane] = o1;
}

extern "C" void kernel_launch(void* const* d_in, const int* in_sizes, int n_in,
                              void* d_out, int out_size)
{
    const int*    head    = (const int*)d_in[0];
    const int*    rel     = (const int*)d_in[1];
    const int*    tail    = (const int*)d_in[2];
    const char*   ent     = (const char*)d_in[3];
    const char*   ent_map = (const char*)d_in[4];
    const float4* rel_emb = (const float4*)d_in[5];
    const float4* rel_map = (const float4*)d_in[6];
    float4*       out     = (float4*)d_out;

    const int threads = 256;  // 8 warps x 2 elems = 16 elems/block
    const int blocks  = BATCH / (WARPS_PER_BLOCK * ELEMS_PER_WARP);  // 1024
    transd_kernel<<<blocks, threads>>>(head, rel, tail, ent, ent_map,
                                       rel_emb, rel_map, out);
}

// round 5
// speedup vs baseline: 1.4982x; 1.1845x over previous
#include <cuda_runtime.h>
#include <cstdint>

// TransD scoring kernel, round 5: HYBRID gathers (LDG + TMA-bulk in parallel).
// out[b] = rp * (dot(hp,h) - dot(tp,t)) + (h - t) + r
// ENT_DIM = REL_DIM = 128, BATCH = 16384.
//
// Model from R1-R4: per-SM outstanding-miss cap (~8KB in flight) binds all
// single-path variants to ~4.4 TB/s warm. Hypothesis: the LDG/L1tex miss
// budget and the TMA/bulk-copy queue are SEPARATE per-SM resources; using
// both at once doubles in-flight bytes. Each warp: elem1 via 4x512B
// cp.async.bulk (issued first), elem0 via 4 LDG.128 into registers; compute
// elem0 while elem1's bulk copies fly.

#define BATCH 16384
#define WARPS_PER_BLOCK 8
#define ELEMS_PER_WARP 2
#define ROW_BYTES 512

__device__ __forceinline__ float warp_sum(float v) {
    v += __shfl_xor_sync(0xFFFFFFFFu, v, 16);
    v += __shfl_xor_sync(0xFFFFFFFFu, v, 8);
    v += __shfl_xor_sync(0xFFFFFFFFu, v, 4);
    v += __shfl_xor_sync(0xFFFFFFFFu, v, 2);
    v += __shfl_xor_sync(0xFFFFFFFFu, v, 1);
    return v;
}

__device__ __forceinline__ uint32_t smem_u32(const void* p) {
    uint32_t a;
    asm("{ .reg .u64 t; cvta.to.shared.u64 t, %1; cvt.u32.u64 %0, t; }"
        : "=r"(a) : "l"(p));
    return a;
}

__device__ __forceinline__ void bulk_ld(uint32_t s_dst, const void* g_src,
                                        uint32_t bytes, uint32_t mbar) {
    asm volatile(
        "cp.async.bulk.shared::cta.global.mbarrier::complete_tx::bytes "
        "[%0], [%1], %2, [%3];\n"
        :: "r"(s_dst), "l"(g_src), "r"(bytes), "r"(mbar) : "memory");
}

__device__ __forceinline__ void mbar_init(uint32_t mbar, uint32_t count) {
    asm volatile("mbarrier.init.shared.b64 [%0], %1;\n" :: "r"(mbar), "r"(count) : "memory");
}

__device__ __forceinline__ void mbar_expect_tx(uint32_t mbar, uint32_t bytes) {
    asm volatile("mbarrier.arrive.expect_tx.shared.b64 _, [%0], %1;\n"
                 :: "r"(mbar), "r"(bytes) : "memory");
}

__device__ __forceinline__ void mbar_wait(uint32_t mbar, uint32_t parity) {
    uint32_t done;
    asm volatile(
        "{\n\t"
        ".reg .pred p;\n\t"
        "mbarrier.try_wait.parity.acquire.cta.shared::cta.b64 p, [%1], %2;\n\t"
        "selp.b32 %0, 1, 0, p;\n\t"
        "}"
        : "=r"(done) : "r"(mbar), "r"(parity) : "memory");
    if (!done) {
        asm volatile(
            "{\n\t"
            ".reg .pred P1;\n\t"
            "WAIT_LOOP_%=:\n\t"
            "mbarrier.try_wait.parity.acquire.cta.shared::cta.b64 P1, [%0], %1, 0x989680;\n\t"
            "@P1 bra.uni WAIT_DONE_%=;\n\t"
            "bra.uni WAIT_LOOP_%=;\n\t"
            "WAIT_DONE_%=:\n\t"
            "}"
            :: "r"(mbar), "r"(parity) : "memory");
    }
}

__global__ __launch_bounds__(256)
void transd_kernel(const int* __restrict__ head,
                   const int* __restrict__ relation,
                   const int* __restrict__ tail,
                   const char* __restrict__ ent_emb,
                   const char* __restrict__ ent_map_emb,
                   const float4* __restrict__ rel_emb,
                   const float4* __restrict__ rel_map_emb,
                   float4* __restrict__ out)
{
    // Per-warp slab: 4 rows (elem1 only) x 512B = 2KB. Block: 16KB.
    __shared__ __align__(128) float4 buf[WARPS_PER_BLOCK][4][32];
    __shared__ __align__(8) unsigned long long mbar_store[WARPS_PER_BLOCK];

    const int wid  = threadIdx.x >> 5;
    const int lane = threadIdx.x & 31;
    const int warp_global = blockIdx.x * WARPS_PER_BLOCK + wid;

    const int b0 = warp_global * ELEMS_PER_WARP;
    const int b1 = b0 + 1;

    const int h0 = head[b0], h1 = head[b1];
    const int t0 = tail[b0], t1 = tail[b1];
    const int r0 = relation[b0], r1 = relation[b1];

    const uint32_t mbar   = smem_u32(&mbar_store[wid]);
    const uint32_t s_row0 = smem_u32(&buf[wid][0][0]);

    // --- Path A: elem1 rows via TMA bulk engine (async into smem) ---
    if (lane == 0) {
        mbar_init(mbar, 1);
        asm volatile("fence.proxy.async.shared::cta;\n" ::: "memory");
        mbar_expect_tx(mbar, 4 * ROW_BYTES);
        bulk_ld(s_row0 + 0 * ROW_BYTES, ent_emb     + (long)h1 * ROW_BYTES, ROW_BYTES, mbar);
        bulk_ld(s_row0 + 1 * ROW_BYTES, ent_emb     + (long)t1 * ROW_BYTES, ROW_BYTES, mbar);
        bulk_ld(s_row0 + 2 * ROW_BYTES, ent_map_emb + (long)h1 * ROW_BYTES, ROW_BYTES, mbar);
        bulk_ld(s_row0 + 3 * ROW_BYTES, ent_map_emb + (long)t1 * ROW_BYTES, ROW_BYTES, mbar);
    }

    // --- Path B: elem0 rows via LDG.128 (L1/MSHR path, registers) ---
    const float4* e4  = (const float4*)ent_emb;
    const float4* em4 = (const float4*)ent_map_emb;
    const long ho0 = (long)h0 * 32 + lane;
    const long to0 = (long)t0 * 32 + lane;
    const float4 vh0  = __ldg(&e4[ho0]);
    const float4 vt0  = __ldg(&e4[to0]);
    const float4 vhp0 = __ldg(&em4[ho0]);
    const float4 vtp0 = __ldg(&em4[to0]);

    // Relations (L2-resident).
    const long ro0 = (long)r0 * 32 + lane;
    const long ro1 = (long)r1 * 32 + lane;
    const float4 vr0  = __ldg(&rel_emb[ro0]);
    const float4 vr1  = __ldg(&rel_emb[ro1]);
    const float4 vrp0 = __ldg(&rel_map_emb[ro0]);
    const float4 vrp1 = __ldg(&rel_map_emb[ro1]);

    // --- Compute elem0 while elem1's bulk copies are still in flight ---
    float dh0 = vh0.x * vhp0.x + vh0.y * vhp0.y + vh0.z * vhp0.z + vh0.w * vhp0.w;
    float dt0 = vt0.x * vtp0.x + vt0.y * vtp0.y + vt0.z * vtp0.z + vt0.w * vtp0.w;
    const float d0 = warp_sum(dh0 - dt0);

    float4 o0;
    o0.x = fmaf(vrp0.x, d0, vh0.x - vt0.x + vr0.x);
    o0.y = fmaf(vrp0.y, d0, vh0.y - vt0.y + vr0.y);
    o0.z = fmaf(vrp0.z, d0, vh0.z - vt0.z + vr0.z);
    o0.w = fmaf(vrp0.w, d0, vh0.w - vt0.w + vr0.w);
    out[(long)b0 * 32 + lane] = o0;

    // --- Wait for elem1, compute it ---
    __syncwarp();
    mbar_wait(mbar, 0);

    const float4 vh1  = buf[wid][0][lane];
    const float4 vt1  = buf[wid][1][lane];
    const float4 vhp1 = buf[wid][2][lane];
    const float4 vtp1 = buf[wid][3][lane];

    float dh1 = vh1.x * vhp1.x + vh1.y * vhp1.y + vh1.z * vhp1.z + vh1.w * vhp1.w;
    float dt1 = vt1.x * vtp1.x + vt1.y * vtp1.y + vt1.z * vtp1.z + vt1.w * vtp1.w;
    const float d1 = warp_sum(dh1 - dt1);

    float4 o1;
    o1.x = fmaf(vrp1.x, d1, vh1.x - vt1.x + vr1.x);
    o1.y = fmaf(vrp1.y, d1, vh1.y - vt1.y + vr1.y);
    o1.z = fmaf(vrp1.z, d1, vh1.z - vt1.z + vr1.z);
    o1.w = fmaf(vrp1.w, d1, vh1.w - vt1.w + vr1.w);
    out[(long)b1 * 32 + lane] = o1;
}

extern "C" void kernel_launch(void* const* d_in, const int* in_sizes, int n_in,
                              void* d_out, int out_size)
{
    const int*    head    = (const int*)d_in[0];
    const int*    rel     = (const int*)d_in[1];
    const int*    tail    = (const int*)d_in[2];
    const char*   ent     = (const char*)d_in[3];
    const char*   ent_map = (const char*)d_in[4];
    const float4* rel_emb = (const float4*)d_in[5];
    const float4* rel_map = (const float4*)d_in[6];
    float4*       out     = (float4*)d_out;

    const int threads = 256;  // 8 warps x 2 elems = 16 elems/block
    const int blocks  = BATCH / (WARPS_PER_BLOCK * ELEMS_PER_WARP);  // 1024
    transd_kernel<<<blocks, threads>>>(head, rel, tail, ent, ent_map,
                                       rel_emb, rel_map, out);
}